// round 13
// baseline (speedup 1.0000x reference)
#include <cuda_runtime.h>
#include <cuda_bf16.h>
#include <cstdint>
#include <math.h>

// ---------------- problem constants ----------------
#define BB 8
#define TQ 8
#define TP 447
#define TC 1500
#define DD 1280
#define HH 20
#define DH 64
#define DFF 5120
#define MM 64              // B*TQ rows
#define TK_SELF (TP + TQ)  // 455

// ---------------- scratch (device globals; no allocation allowed) ----------------
__device__ float g_xl_[MM * DD];
__device__ float g_q_[MM * DD];
__device__ float g_attn_[MM * DD];
__device__ float g_x1_[MM * DD];
__device__ float g_h_[MM * DFF];
__device__ float g_part_[4915200];                  // split-K partials
__device__ float g_apacc_[32 * BB * HH * TQ * DH];  // attn split partial acc (32 slots)
__device__ float g_aml_[32 * BB * HH * 16];         // attn split (m,l) per q

// ---------------- helpers ----------------
__device__ __forceinline__ uint32_t smem_to_u32(const void* p) {
    uint32_t a;
    asm("{ .reg .u64 t; cvta.to.shared.u64 t, %1; cvt.u32.u64 %0, t; }" : "=r"(a) : "l"(p));
    return a;
}
__device__ __forceinline__ uint32_t f2tf(float f) {
    uint32_t r;
    asm("cvt.rna.tf32.f32 %0, %1;" : "=r"(r) : "f"(f));
    return r;
}
#define LDMX4(r0, r1, r2, r3, addr) \
    asm volatile("ldmatrix.sync.aligned.m8n8.x4.shared.b16 {%0,%1,%2,%3}, [%4];" \
                 : "=r"(r0), "=r"(r1), "=r"(r2), "=r"(r3) : "r"(addr))
__device__ __forceinline__ void mma_tf32(float c[4], uint32_t a0, uint32_t a1,
                                         uint32_t a2, uint32_t a3,
                                         uint32_t b0, uint32_t b1) {
    asm volatile(
        "mma.sync.aligned.m16n8k8.row.col.f32.tf32.tf32.f32 "
        "{%0,%1,%2,%3}, {%4,%5,%6,%7}, {%8,%9}, {%0,%1,%2,%3};"
        : "+f"(c[0]), "+f"(c[1]), "+f"(c[2]), "+f"(c[3])
        : "r"(a0), "r"(a1), "r"(a2), "r"(a3), "r"(b0), "r"(b1));
}
#define CP_ASYNC16(saddr, gptr) \
    asm volatile("cp.async.cg.shared.global [%0], [%1], 16;" :: "r"(saddr), "l"(gptr))
#define CP_COMMIT() asm volatile("cp.async.commit_group;" ::: "memory")
#define CP_WAIT1() asm volatile("cp.async.wait_group 1;" ::: "memory")
#define CP_WAIT0() asm volatile("cp.async.wait_group 0;" ::: "memory")

// ---------------- LayerNorm: one block per row ----------------
__global__ __launch_bounds__(256) void ln_kernel(const float* __restrict__ x,
                                                 const float* __restrict__ w,
                                                 const float* __restrict__ b,
                                                 float* __restrict__ out) {
    int row = blockIdx.x;
    const float* xr = x + (size_t)row * DD;
    __shared__ float red0[32], red1[32];
    float s = 0.f, s2 = 0.f;
    for (int i = threadIdx.x; i < DD; i += 256) {
        float v = xr[i];
        s += v;
        s2 += v * v;
    }
    for (int o = 16; o; o >>= 1) {
        s += __shfl_xor_sync(~0u, s, o);
        s2 += __shfl_xor_sync(~0u, s2, o);
    }
    int lane = threadIdx.x & 31, wid = threadIdx.x >> 5;
    if (lane == 0) { red0[wid] = s; red1[wid] = s2; }
    __syncthreads();
    if (wid == 0) {
        s = (lane < 8) ? red0[lane] : 0.f;
        s2 = (lane < 8) ? red1[lane] : 0.f;
        for (int o = 4; o; o >>= 1) {
            s += __shfl_xor_sync(~0u, s, o);
            s2 += __shfl_xor_sync(~0u, s2, o);
        }
        if (lane == 0) { red0[0] = s; red1[0] = s2; }
    }
    __syncthreads();
    float m = red0[0] * (1.f / DD);
    float var = red1[0] * (1.f / DD) - m * m;
    float inv = rsqrtf(var + 1e-5f);
    for (int i = threadIdx.x; i < DD; i += 256) {
        out[(size_t)row * DD + i] = (xr[i] - m) * inv * w[i] + b[i];
    }
}

// ---------------- mma.sync tf32 split-K GEMM ----------------
#define SA 36   // smem row stride in floats

__global__ __launch_bounds__(256) void gemm_mma(const float* __restrict__ A,
                                                const float* __restrict__ W0,
                                                const float* __restrict__ W1,
                                                const float* __restrict__ W2,
                                                float* __restrict__ part,
                                                int K, int N, int kc) {
    __shared__ __align__(16) uint32_t As[2][64 * SA];
    __shared__ __align__(16) uint32_t Bs[2][64 * SA];
    int tid = threadIdx.x, lane = tid & 31, w = tid >> 5;
    int wm = w & 3, wn = w >> 2;
    int n0 = blockIdx.x * 64;
    int slab = blockIdx.y;
    const float* W = (slab == 0) ? W0 : ((slab == 1) ? W1 : W2);
    int z = blockIdx.z, k0 = z * kc;
    int nst = kc >> 5;

    int a_row = wm * 16 + ((lane >> 3) & 1) * 8 + (lane & 7);
    uint32_t a_koff = ((lane >> 4) & 1) * 16;
    int b_row_off = ((lane >> 4) & 1) * 8 + (lane & 7);
    uint32_t b_koff = ((lane >> 3) & 1) * 16;
    uint32_t aAddr0 = smem_to_u32(&As[0][0]) + (uint32_t)(a_row * SA) * 4 + a_koff;
    uint32_t bAddr0 = smem_to_u32(&Bs[0][0]) + b_koff;

    int s_row = tid >> 2, s_c4 = tid & 3;
    int s_n = tid & 63, s_k = tid >> 6;

    float c[4][4];
#pragma unroll
    for (int j = 0; j < 4; j++)
#pragma unroll
        for (int i = 0; i < 4; i++) c[j][i] = 0.f;

    {
        const float* ar = A + (size_t)s_row * K + k0;
        float4 v0 = *(const float4*)(ar + s_c4 * 4);
        float4 v1 = *(const float4*)(ar + (s_c4 + 4) * 4);
        uint4 u0 = make_uint4(f2tf(v0.x), f2tf(v0.y), f2tf(v0.z), f2tf(v0.w));
        uint4 u1 = make_uint4(f2tf(v1.x), f2tf(v1.y), f2tf(v1.z), f2tf(v1.w));
        *(uint4*)&As[0][s_row * SA + s_c4 * 4] = u0;
        *(uint4*)&As[0][s_row * SA + (s_c4 + 4) * 4] = u1;
        const float* wp = W + (size_t)k0 * N + n0 + s_n;
#pragma unroll
        for (int j = 0; j < 8; j++) {
            int k2 = s_k + j * 4;
            Bs[0][s_n * SA + k2] = f2tf(wp[(size_t)k2 * N]);
        }
    }
    __syncthreads();

    for (int st = 0; st < nst; st++) {
        int buf = st & 1;
        float4 pa0, pa1;
        float pb[8];
        if (st + 1 < nst) {
            int kb = k0 + (st + 1) * 32;
            const float* ar = A + (size_t)s_row * K + kb;
            pa0 = *(const float4*)(ar + s_c4 * 4);
            pa1 = *(const float4*)(ar + (s_c4 + 4) * 4);
            const float* wp = W + (size_t)kb * N + n0 + s_n;
#pragma unroll
            for (int j = 0; j < 8; j++) pb[j] = wp[(size_t)(s_k + j * 4) * N];
        }
        uint32_t aB = aAddr0 + (uint32_t)buf * 64 * SA * 4;
#pragma unroll
        for (int s = 0; s < 4; s++) {
            uint32_t a0, a1, a2, a3;
            LDMX4(a0, a1, a2, a3, aB + s * 32);
#pragma unroll
            for (int jp = 0; jp < 2; jp++) {
                uint32_t b0, b1, b2, b3;
                uint32_t baddr = bAddr0 + (uint32_t)buf * 64 * SA * 4 +
                                 (uint32_t)((wn * 32 + jp * 16 + b_row_off) * SA) * 4 + s * 32;
                LDMX4(b0, b1, b2, b3, baddr);
                mma_tf32(c[jp * 2], a0, a1, a2, a3, b0, b1);
                mma_tf32(c[jp * 2 + 1], a0, a1, a2, a3, b2, b3);
            }
        }
        if (st + 1 < nst) {
            int nb = buf ^ 1;
            uint4 u0 = make_uint4(f2tf(pa0.x), f2tf(pa0.y), f2tf(pa0.z), f2tf(pa0.w));
            uint4 u1 = make_uint4(f2tf(pa1.x), f2tf(pa1.y), f2tf(pa1.z), f2tf(pa1.w));
            *(uint4*)&As[nb][s_row * SA + s_c4 * 4] = u0;
            *(uint4*)&As[nb][s_row * SA + (s_c4 + 4) * 4] = u1;
#pragma unroll
            for (int j = 0; j < 8; j++)
                Bs[nb][s_n * SA + s_k + j * 4] = f2tf(pb[j]);
            __syncthreads();
        }
    }

    int g = lane >> 2, t = lane & 3;
    float* po = part + ((size_t)z * gridDim.y + slab) * MM * N;
#pragma unroll
    for (int j = 0; j < 4; j++) {
        int col = n0 + wn * 32 + j * 8 + 2 * t;
        int r0 = wm * 16 + g;
        *(float2*)&po[(size_t)r0 * N + col] = make_float2(c[j][0], c[j][1]);
        *(float2*)&po[(size_t)(r0 + 8) * N + col] = make_float2(c[j][2], c[j][3]);
    }
}

// ---------------- reduce partials + epilogue (multi-slab) ----------------
__global__ __launch_bounds__(256) void reduce_epi(const float* __restrict__ part, int nz,
                                                  int MN, int N,
                                                  const float* __restrict__ b0,
                                                  const float* __restrict__ b1,
                                                  const float* __restrict__ b2,
                                                  const float* __restrict__ res,
                                                  float* __restrict__ o0,
                                                  float* __restrict__ o1,
                                                  float* __restrict__ o2,
                                                  int dogelu) {
    int i = blockIdx.x * 256 + threadIdx.x;
    if (i >= MN) return;
    int slab = blockIdx.y;
    int nslab = gridDim.y;
    const float* bias = (slab == 0) ? b0 : ((slab == 1) ? b1 : b2);
    float* out = (slab == 0) ? o0 : ((slab == 1) ? o1 : o2);
    float s = 0.f;
    for (int z = 0; z < nz; z++) s += part[((size_t)z * nslab + slab) * MN + i];
    if (bias) s += bias[i % N];
    if (dogelu) s = 0.5f * s * (1.f + erff(s * 0.70710678118654752440f));
    if (res) s += res[i];
    out[i] = s;
}

// ---------------- attention split kernel: ONE <=64-key tile per CTA ----------
// K and V cp.async loads issued back-to-back at kernel entry (2 commit groups)
// so their DRAM latencies fully overlap. mma scores; striped AV.
#define ATILE 64
#define KT_F (ATILE * 68)     // floats per tile buffer
#define REDS 66               // reduce-buffer row stride

__device__ __forceinline__ void stage_tile1(uint32_t dst, const float* cache,
                                            const float* neu, int b, int h, int Tc,
                                            int kgbase, int nk, int srow, int sq4) {
    if (srow < nk) {
        int kg = kgbase + srow;
        const float* src = (kg < Tc)
            ? cache + ((size_t)b * Tc + kg) * DD + h * DH
            : neu + (size_t)(b * TQ + (kg - Tc)) * DD + h * DH;
        uint32_t d = dst + (uint32_t)(srow * 68) * 4;
#pragma unroll
        for (int j = 0; j < 4; j++)
            CP_ASYNC16(d + (uint32_t)((sq4 + j) * 16), src + (sq4 + j) * 4);
    }
}

__global__ __launch_bounds__(256) void attn_split(const float* __restrict__ kq,
                                                  const float* __restrict__ kc,
                                                  const float* __restrict__ vc,
                                                  const float* __restrict__ kn,
                                                  const float* __restrict__ vn,
                                                  const float* __restrict__ mask,
                                                  float* __restrict__ apacc,
                                                  float* __restrict__ aml,
                                                  int Tk, int Tc, int chunk) {
    __shared__ float sc[8 * ATILE];
    __shared__ __align__(16) float kt[2][KT_F];   // [0]=K tile, [1]=V tile
    __shared__ float qs[8 * 68];
    __shared__ float ml[16];

    int h = blockIdx.x, b = blockIdx.y, z = blockIdx.z;
    int k0 = z * chunk;
    int nv = min(Tk, k0 + chunk) - k0;
    if (nv <= 0) nv = 0;
    int tid = threadIdx.x, lane = tid & 31, w = tid >> 5;
    uint32_t ktb = smem_to_u32(&kt[0][0]);

    int srow = tid >> 2, sq4 = (tid & 3) * 4;

    // ---- issue K then V loads immediately; latencies overlap ----
    stage_tile1(ktb, kc, kn, b, h, Tc, k0, nv, srow, sq4);
    CP_COMMIT();                                   // group: K
    stage_tile1(ktb + (uint32_t)KT_F * 4, vc, vn, b, h, Tc, k0, nv, srow, sq4);
    CP_COMMIT();                                   // group: V

    // ---- stage q while loads are in flight ----
    if (tid < 128) {
        int qi = tid >> 4, d4 = (tid & 15) * 4;
        float4 v = *(const float4*)(kq + (size_t)(b * TQ + qi) * DD + h * DH + d4);
        v.x *= 0.125f; v.y *= 0.125f; v.z *= 0.125f; v.w *= 0.125f;
        *(float4*)&qs[qi * 68 + d4] = v;
    }
    __syncthreads();

    // A fragments: q rows 0..7 (rows 8..15 of m16 are zero)
    uint32_t aA[8], aC[8];
    const uint32_t zr = 0;
    {
        const float* qp = &qs[(lane >> 2) * 68];
#pragma unroll
        for (int s = 0; s < 8; s++) {
            aA[s] = f2tf(qp[s * 8 + (lane & 3)]);
            aC[s] = f2tf(qp[s * 8 + 4 + (lane & 3)]);
        }
    }

    // ---- wait K; scores via mma ----
    CP_WAIT1();
    __syncthreads();
    {
        float c0[4] = {0.f, 0.f, 0.f, 0.f};
        uint32_t kaddr = ktb + (uint32_t)((w * 8 + (lane & 7)) * 68) * 4 +
                         ((lane >> 3) & 3) * 16;
#pragma unroll
        for (int s = 0; s < 4; s++) {
            uint32_t b0, b1, b2, b3;
            LDMX4(b0, b1, b2, b3, kaddr + s * 64);
            mma_tf32(c0, aA[2 * s], zr, aC[2 * s], zr, b0, b1);
            mma_tf32(c0, aA[2 * s + 1], zr, aC[2 * s + 1], zr, b2, b3);
        }
        int qrow = lane >> 2;
        int key = w * 8 + 2 * (lane & 3);
        if (key < nv) {
            float s0 = c0[0];
            if (mask) s0 += mask[(size_t)qrow * Tk + k0 + key];
            sc[qrow * ATILE + key] = s0;
        }
        if (key + 1 < nv) {
            float s1 = c0[1];
            if (mask) s1 += mask[(size_t)qrow * Tk + k0 + key + 1];
            sc[qrow * ATILE + key + 1] = s1;
        }
    }
    __syncthreads();

    // ---- partial softmax: warp w owns q row w ----
    {
        float m = -1e30f;
        for (int k = lane; k < nv; k += 32) m = fmaxf(m, sc[w * ATILE + k]);
        for (int o = 16; o; o >>= 1) m = fmaxf(m, __shfl_xor_sync(~0u, m, o));
        float l = 0.f;
        for (int k = lane; k < nv; k += 32) {
            float e = __expf(sc[w * ATILE + k] - m);
            sc[w * ATILE + k] = e;
            l += e;
        }
        for (int o = 16; o; o >>= 1) l += __shfl_xor_sync(~0u, l, o);
        if (lane == 0) { ml[w * 2] = m; ml[w * 2 + 1] = l; }
    }

    // ---- wait V (usually already landed); striped AV ----
    CP_WAIT0();
    __syncthreads();
    float acc[8][2];
#pragma unroll
    for (int qi = 0; qi < 8; qi++) { acc[qi][0] = 0.f; acc[qi][1] = 0.f; }
    {
        const float* vt = &kt[1][0];
        for (int k = w; k < nv; k += 8) {
            float2 v2 = *(const float2*)&vt[k * 68 + 2 * lane];
            const float* sp = &sc[k];
#pragma unroll
            for (int qi = 0; qi < 8; qi++) {
                float p = sp[qi * ATILE];
                acc[qi][0] += p * v2.x;
                acc[qi][1] += p * v2.y;
            }
        }
    }
    __syncthreads();

    // ---- cross-warp reduce (aliased onto kt[0], no longer needed) ----
    float* red = (float*)&kt[0][0];
#pragma unroll
    for (int qi = 0; qi < 8; qi++)
        *(float2*)&red[(w * 8 + qi) * REDS + 2 * lane] = make_float2(acc[qi][0], acc[qi][1]);
    __syncthreads();

    size_t idx = ((size_t)z * BB + b) * HH + h;
    float* ap = apacc + idx * TQ * DH;
    int qi2 = tid >> 5, dp = tid & 31;
    float s0 = 0.f, s1 = 0.f;
#pragma unroll
    for (int ww = 0; ww < 8; ww++) {
        float2 a = *(const float2*)&red[(ww * 8 + qi2) * REDS + 2 * dp];
        s0 += a.x;
        s1 += a.y;
    }
    *(float2*)&ap[qi2 * 64 + 2 * dp] = make_float2(s0, s1);
    if (tid < 16) aml[idx * 16 + tid] = ml[tid];
}

// ---------------- attention combine ----------------
__global__ __launch_bounds__(256) void attn_combine(const float* __restrict__ apacc,
                                                    const float* __restrict__ aml,
                                                    float* __restrict__ out, int S,
                                                    int Tk, int chunk) {
    int h = blockIdx.x, b = blockIdx.y;
    int tid = threadIdx.x;
    int qi = tid >> 5, dp = tid & 31;
    float mstar = -1e30f;
    for (int z = 0; z < S; z++) {
        if (z * chunk >= Tk) break;
        size_t idx = ((size_t)z * BB + b) * HH + h;
        mstar = fmaxf(mstar, aml[idx * 16 + qi * 2]);
    }
    float den = 0.f, n0 = 0.f, n1 = 0.f;
    for (int z = 0; z < S; z++) {
        if (z * chunk >= Tk) break;
        size_t idx = ((size_t)z * BB + b) * HH + h;
        float mz = aml[idx * 16 + qi * 2];
        float lz = aml[idx * 16 + qi * 2 + 1];
        float s = __expf(mz - mstar);
        den += lz * s;
        float2 a = *(const float2*)&apacc[idx * TQ * DH + qi * 64 + dp * 2];
        n0 += a.x * s;
        n1 += a.y * s;
    }
    float inv = 1.f / den;
    float* o = out + (size_t)(b * TQ + qi) * DD + h * DH + dp * 2;
    o[0] = n0 * inv;
    o[1] = n1 * inv;
}

// ---------------- host orchestration ----------------
extern "C" void kernel_launch(void* const* d_in, const int* in_sizes, int n_in,
                              void* d_out, int out_size) {
    const float* x            = (const float*)d_in[0];
    const float* self_k_cache = (const float*)d_in[1];
    const float* self_v_cache = (const float*)d_in[2];
    const float* cross_k      = (const float*)d_in[3];
    const float* cross_v      = (const float*)d_in[4];
    const float* mask         = (const float*)d_in[5];
    const float* attn_wq = (const float*)d_in[6];
    const float* attn_bq = (const float*)d_in[7];
    const float* attn_wk = (const float*)d_in[8];
    const float* attn_wv = (const float*)d_in[9];
    const float* attn_bv = (const float*)d_in[10];
    const float* attn_wo = (const float*)d_in[11];
    const float* attn_bo = (const float*)d_in[12];
    const float* cross_wq = (const float*)d_in[13];
    const float* cross_bq = (const float*)d_in[14];
    const float* cross_wo = (const float*)d_in[15];
    const float* cross_bo = (const float*)d_in[16];
    const float* attn_ln_w = (const float*)d_in[17];
    const float* attn_ln_b = (const float*)d_in[18];
    const float* cross_ln_w = (const float*)d_in[19];
    const float* cross_ln_b = (const float*)d_in[20];
    const float* mlp_ln_w = (const float*)d_in[21];
    const float* mlp_ln_b = (const float*)d_in[22];
    const float* mlp_w1 = (const float*)d_in[23];
    const float* mlp_b1 = (const float*)d_in[24];
    const float* mlp_w2 = (const float*)d_in[25];
    const float* mlp_b2 = (const float*)d_in[26];

    float* out_x  = (float*)d_out;
    float* out_k1 = out_x + MM * DD;
    float* out_v1 = out_k1 + MM * DD;

    float *g_xl, *g_q, *g_attn, *g_x1, *g_h, *g_part, *g_apacc, *g_aml;
    cudaGetSymbolAddress((void**)&g_xl, g_xl_);
    cudaGetSymbolAddress((void**)&g_q, g_q_);
    cudaGetSymbolAddress((void**)&g_attn, g_attn_);
    cudaGetSymbolAddress((void**)&g_x1, g_x1_);
    cudaGetSymbolAddress((void**)&g_h, g_h_);
    cudaGetSymbolAddress((void**)&g_part, g_part_);
    cudaGetSymbolAddress((void**)&g_apacc, g_apacc_);
    cudaGetSymbolAddress((void**)&g_aml, g_aml_);

    const int MN_D = MM * DD;        // 81920
    const int MN_F = MM * DFF;       // 327680
    dim3 blk(256);

    dim3 gQKV(DD / 64, 3, 10);   // fused QKV: kc=128 (4 stages), 600 CTAs
    dim3 gD(DD / 64, 1, 20);     // D GEMM: kc=64 (2 stages), 400 CTAs
    dim3 gF1(DFF / 64, 1, 8);    // MLP1: kc=160 (5 stages), 640 CTAs
    dim3 gF2(DD / 64, 1, 20);    // MLP2: kc=256 (8 stages), 400 CTAs
    int redD = (MN_D + 255) / 256;
    int redF = (MN_F + 255) / 256;

    int S_SELF = 8, CH_SELF = (TK_SELF + S_SELF - 1) / S_SELF;   // 57 (<=64)
    int S_CROSS = 24, CH_CROSS = (TC + S_CROSS - 1) / S_CROSS;   // 63 (<=64)

    // --- self-attention block ---
    ln_kernel<<<MM, blk>>>(x, attn_ln_w, attn_ln_b, g_xl);

    gemm_mma<<<gQKV, blk>>>(g_xl, attn_wq, attn_wk, attn_wv, g_part, DD, DD, 128);
    reduce_epi<<<dim3(redD, 3), blk>>>(g_part, 10, MN_D, DD,
                                       attn_bq, nullptr, attn_bv, nullptr,
                                       g_q, out_k1, out_v1, 0);

    attn_split<<<dim3(HH, BB, S_SELF), blk>>>(g_q, self_k_cache, self_v_cache,
                                              out_k1, out_v1, mask,
                                              g_apacc, g_aml, TK_SELF, TP, CH_SELF);
    attn_combine<<<dim3(HH, BB), blk>>>(g_apacc, g_aml, g_attn, S_SELF, TK_SELF, CH_SELF);

    gemm_mma<<<gD, blk>>>(g_attn, attn_wo, attn_wo, attn_wo, g_part, DD, DD, 64);
    reduce_epi<<<dim3(redD, 1), blk>>>(g_part, 20, MN_D, DD,
                                       attn_bo, nullptr, nullptr, x,
                                       g_x1, nullptr, nullptr, 0);

    // --- cross-attention block ---
    ln_kernel<<<MM, blk>>>(g_x1, cross_ln_w, cross_ln_b, g_xl);

    gemm_mma<<<gD, blk>>>(g_xl, cross_wq, cross_wq, cross_wq, g_part, DD, DD, 64);
    reduce_epi<<<dim3(redD, 1), blk>>>(g_part, 20, MN_D, DD,
                                       cross_bq, nullptr, nullptr, nullptr,
                                       g_q, nullptr, nullptr, 0);

    attn_split<<<dim3(HH, BB, S_CROSS), blk>>>(g_q, cross_k, cross_v,
                                               nullptr, nullptr, nullptr,
                                               g_apacc, g_aml, TC, TC, CH_CROSS);
    attn_combine<<<dim3(HH, BB), blk>>>(g_apacc, g_aml, g_attn, S_CROSS, TC, CH_CROSS);

    gemm_mma<<<gD, blk>>>(g_attn, cross_wo, cross_wo, cross_wo, g_part, DD, DD, 64);
    reduce_epi<<<dim3(redD, 1), blk>>>(g_part, 20, MN_D, DD,
                                       cross_bo, nullptr, nullptr, g_x1,
                                       out_x, nullptr, nullptr, 0);

    // --- MLP block ---
    ln_kernel<<<MM, blk>>>(out_x, mlp_ln_w, mlp_ln_b, g_xl);

    gemm_mma<<<gF1, blk>>>(g_xl, mlp_w1, mlp_w1, mlp_w1, g_part, DD, DFF, 160);
    reduce_epi<<<dim3(redF, 1), blk>>>(g_part, 8, MN_F, DFF,
                                       mlp_b1, nullptr, nullptr, nullptr,
                                       g_h, nullptr, nullptr, 1);

    gemm_mma<<<gF2, blk>>>(g_h, mlp_w2, mlp_w2, mlp_w2, g_part, DFF, DD, 256);
    reduce_epi<<<dim3(redD, 1), blk>>>(g_part, 20, MN_D, DD,
                                       mlp_b2, nullptr, nullptr, out_x,
                                       out_x, nullptr, nullptr, 0);
}

// round 15
// speedup vs baseline: 1.1377x; 1.1377x over previous
#include <cuda_runtime.h>
#include <cuda_bf16.h>
#include <cstdint>
#include <math.h>

// ---------------- problem constants ----------------
#define BB 8
#define TQ 8
#define TP 447
#define TC 1500
#define DD 1280
#define HH 20
#define DH 64
#define DFF 5120
#define MM 64              // B*TQ rows
#define TK_SELF (TP + TQ)  // 455

// ---------------- scratch (device globals; no allocation allowed) ----------------
__device__ float g_xl_[MM * DD];
__device__ float g_q_[MM * DD];
__device__ float g_attn_[MM * DD];
__device__ float g_x1_[MM * DD];
__device__ float g_h_[MM * DFF];
__device__ float g_part_[4915200];                  // split-K partials
__device__ float g_apacc_[32 * BB * HH * TQ * DH];  // attn split partial acc
__device__ float g_aml_[32 * BB * HH * 16];         // attn split (m,l) per q

// ---------------- helpers ----------------
__device__ __forceinline__ uint32_t smem_to_u32(const void* p) {
    uint32_t a;
    asm("{ .reg .u64 t; cvta.to.shared.u64 t, %1; cvt.u32.u64 %0, t; }" : "=r"(a) : "l"(p));
    return a;
}
__device__ __forceinline__ uint32_t f2tf(float f) {
    uint32_t r;
    asm("cvt.rna.tf32.f32 %0, %1;" : "=r"(r) : "f"(f));
    return r;
}
#define LDMX4(r0, r1, r2, r3, addr) \
    asm volatile("ldmatrix.sync.aligned.m8n8.x4.shared.b16 {%0,%1,%2,%3}, [%4];" \
                 : "=r"(r0), "=r"(r1), "=r"(r2), "=r"(r3) : "r"(addr))
__device__ __forceinline__ void mma_tf32(float c[4], uint32_t a0, uint32_t a1,
                                         uint32_t a2, uint32_t a3,
                                         uint32_t b0, uint32_t b1) {
    asm volatile(
        "mma.sync.aligned.m16n8k8.row.col.f32.tf32.tf32.f32 "
        "{%0,%1,%2,%3}, {%4,%5,%6,%7}, {%8,%9}, {%0,%1,%2,%3};"
        : "+f"(c[0]), "+f"(c[1]), "+f"(c[2]), "+f"(c[3])
        : "r"(a0), "r"(a1), "r"(a2), "r"(a3), "r"(b0), "r"(b1));
}
#define CP_ASYNC16(saddr, gptr) \
    asm volatile("cp.async.cg.shared.global [%0], [%1], 16;" :: "r"(saddr), "l"(gptr))
#define CP_ASYNC4(saddr, gptr) \
    asm volatile("cp.async.ca.shared.global [%0], [%1], 4;" :: "r"(saddr), "l"(gptr))
#define CP_COMMIT() asm volatile("cp.async.commit_group;" ::: "memory")
#define CP_WAIT1() asm volatile("cp.async.wait_group 1;" ::: "memory")
#define CP_WAIT0() asm volatile("cp.async.wait_group 0;" ::: "memory")

// ---------------- LayerNorm: one block per row ----------------
__global__ __launch_bounds__(256) void ln_kernel(const float* __restrict__ x,
                                                 const float* __restrict__ w,
                                                 const float* __restrict__ b,
                                                 float* __restrict__ out) {
    int row = blockIdx.x;
    const float* xr = x + (size_t)row * DD;
    __shared__ float red0[32], red1[32];
    float s = 0.f, s2 = 0.f;
    for (int i = threadIdx.x; i < DD; i += 256) {
        float v = xr[i];
        s += v;
        s2 += v * v;
    }
    for (int o = 16; o; o >>= 1) {
        s += __shfl_xor_sync(~0u, s, o);
        s2 += __shfl_xor_sync(~0u, s2, o);
    }
    int lane = threadIdx.x & 31, wid = threadIdx.x >> 5;
    if (lane == 0) { red0[wid] = s; red1[wid] = s2; }
    __syncthreads();
    if (wid == 0) {
        s = (lane < 8) ? red0[lane] : 0.f;
        s2 = (lane < 8) ? red1[lane] : 0.f;
        for (int o = 4; o; o >>= 1) {
            s += __shfl_xor_sync(~0u, s, o);
            s2 += __shfl_xor_sync(~0u, s2, o);
        }
        if (lane == 0) { red0[0] = s; red1[0] = s2; }
    }
    __syncthreads();
    float m = red0[0] * (1.f / DD);
    float var = red1[0] * (1.f / DD) - m * m;
    float inv = rsqrtf(var + 1e-5f);
    for (int i = threadIdx.x; i < DD; i += 256) {
        out[(size_t)row * DD + i] = (xr[i] - m) * inv * w[i] + b[i];
    }
}

// ---------------- mma.sync tf32 split-K GEMM (cp.async staging) ----------------
// fp32 bits staged raw; tensor core truncates to tf32 internally.
#define SA 36   // smem row stride in floats (144B = 9x16B, keeps 16B alignment)

__global__ __launch_bounds__(256) void gemm_mma(const float* __restrict__ A,
                                                const float* __restrict__ W0,
                                                const float* __restrict__ W1,
                                                const float* __restrict__ W2,
                                                float* __restrict__ part,
                                                int K, int N, int kc) {
    __shared__ __align__(16) uint32_t As[2][64 * SA];
    __shared__ __align__(16) uint32_t Bs[2][64 * SA];
    int tid = threadIdx.x, lane = tid & 31, w = tid >> 5;
    int wm = w & 3, wn = w >> 2;
    int n0 = blockIdx.x * 64;
    int slab = blockIdx.y;
    const float* W = (slab == 0) ? W0 : ((slab == 1) ? W1 : W2);
    int z = blockIdx.z, k0 = z * kc;
    int nst = kc >> 5;

    int a_row = wm * 16 + ((lane >> 3) & 1) * 8 + (lane & 7);
    uint32_t a_koff = ((lane >> 4) & 1) * 16;
    int b_row_off = ((lane >> 4) & 1) * 8 + (lane & 7);
    uint32_t b_koff = ((lane >> 3) & 1) * 16;
    uint32_t aAddr0 = smem_to_u32(&As[0][0]) + (uint32_t)(a_row * SA) * 4 + a_koff;
    uint32_t bAddr0 = smem_to_u32(&Bs[0][0]) + b_koff;
    uint32_t aSmem = smem_to_u32(&As[0][0]);
    uint32_t bSmem = smem_to_u32(&Bs[0][0]);

    int s_row = tid >> 2, s_c4 = tid & 3;   // A: 2 x 16B per thread
    int s_n = tid & 63, s_k = tid >> 6;     // B: 8 x 4B per thread (coalesced in n)

    // stage k-block s into buffer buf (async)
    auto stage = [&](int s, int buf) {
        const float* ar = A + (size_t)s_row * K + k0 + s * 32;
        uint32_t ad = aSmem + (uint32_t)(buf * 64 * SA + s_row * SA) * 4;
        CP_ASYNC16(ad + (uint32_t)(s_c4 * 16), ar + s_c4 * 4);
        CP_ASYNC16(ad + (uint32_t)((s_c4 + 4) * 16), ar + (s_c4 + 4) * 4);
        const float* wp = W + (size_t)(k0 + s * 32) * N + n0 + s_n;
        uint32_t bd = bSmem + (uint32_t)(buf * 64 * SA + s_n * SA) * 4;
#pragma unroll
        for (int j = 0; j < 8; j++) {
            int k2 = s_k + j * 4;
            CP_ASYNC4(bd + (uint32_t)(k2 * 4), wp + (size_t)k2 * N);
        }
    };

    float c[4][4];
#pragma unroll
    for (int j = 0; j < 4; j++)
#pragma unroll
        for (int i = 0; i < 4; i++) c[j][i] = 0.f;

    stage(0, 0);
    CP_COMMIT();
    if (nst > 1) { stage(1, 1); CP_COMMIT(); }

    for (int st = 0; st < nst; st++) {
        if (st + 1 < nst) { CP_WAIT1(); } else { CP_WAIT0(); }
        __syncthreads();
        int buf = st & 1;
        uint32_t aB = aAddr0 + (uint32_t)buf * 64 * SA * 4;
#pragma unroll
        for (int s = 0; s < 4; s++) {
            uint32_t a0, a1, a2, a3;
            LDMX4(a0, a1, a2, a3, aB + s * 32);
#pragma unroll
            for (int jp = 0; jp < 2; jp++) {
                uint32_t b0, b1, b2, b3;
                uint32_t baddr = bAddr0 + (uint32_t)buf * 64 * SA * 4 +
                                 (uint32_t)((wn * 32 + jp * 16 + b_row_off) * SA) * 4 + s * 32;
                LDMX4(b0, b1, b2, b3, baddr);
                mma_tf32(c[jp * 2], a0, a1, a2, a3, b0, b1);
                mma_tf32(c[jp * 2 + 1], a0, a1, a2, a3, b2, b3);
            }
        }
        if (st + 2 < nst) {
            __syncthreads();           // all warps done reading buf before refill
            stage(st + 2, buf);
            CP_COMMIT();
        }
    }

    int g = lane >> 2, t = lane & 3;
    float* po = part + ((size_t)z * gridDim.y + slab) * MM * N;
#pragma unroll
    for (int j = 0; j < 4; j++) {
        int col = n0 + wn * 32 + j * 8 + 2 * t;
        int r0 = wm * 16 + g;
        *(float2*)&po[(size_t)r0 * N + col] = make_float2(c[j][0], c[j][1]);
        *(float2*)&po[(size_t)(r0 + 8) * N + col] = make_float2(c[j][2], c[j][3]);
    }
}

// ---------------- reduce partials + epilogue (multi-slab) ----------------
__global__ __launch_bounds__(256) void reduce_epi(const float* __restrict__ part, int nz,
                                                  int MN, int N,
                                                  const float* __restrict__ b0,
                                                  const float* __restrict__ b1,
                                                  const float* __restrict__ b2,
                                                  const float* __restrict__ res,
                                                  float* __restrict__ o0,
                                                  float* __restrict__ o1,
                                                  float* __restrict__ o2,
                                                  int dogelu) {
    int i = blockIdx.x * 256 + threadIdx.x;
    if (i >= MN) return;
    int slab = blockIdx.y;
    int nslab = gridDim.y;
    const float* bias = (slab == 0) ? b0 : ((slab == 1) ? b1 : b2);
    float* out = (slab == 0) ? o0 : ((slab == 1) ? o1 : o2);
    float s = 0.f;
    for (int z = 0; z < nz; z++) s += part[((size_t)z * nslab + slab) * MN + i];
    if (bias) s += bias[i % N];
    if (dogelu) s = 0.5f * s * (1.f + erff(s * 0.70710678118654752440f));
    if (res) s += res[i];
    out[i] = s;
}

// ======================= attention kernels =======================
#define ATILE 64
#define KT_F (ATILE * 68)
#define REDS 66
#define SCP 152

__device__ __forceinline__ void stage_rows(uint32_t dst, const float* cache,
                                           const float* neu, int b, int h, int Tc,
                                           int kgbase, int nk, int srow, int sq4) {
    if (srow < nk) {
        int kg = kgbase + srow;
        const float* src = (kg < Tc)
            ? cache + ((size_t)b * Tc + kg) * DD + h * DH
            : neu + (size_t)(b * TQ + (kg - Tc)) * DD + h * DH;
        uint32_t d = dst + (uint32_t)(srow * 68) * 4;
#pragma unroll
        for (int j = 0; j < 4; j++)
            CP_ASYNC16(d + (uint32_t)((sq4 + j) * 16), src + (sq4 + j) * 4);
    }
}

// ---- single-tile kernel (<=64 keys per CTA); K+V loads fully overlapped ----
__global__ __launch_bounds__(256) void attn_split_1t(const float* __restrict__ kq,
                                                     const float* __restrict__ kc,
                                                     const float* __restrict__ vc,
                                                     const float* __restrict__ kn,
                                                     const float* __restrict__ vn,
                                                     const float* __restrict__ mask,
                                                     float* __restrict__ apacc,
                                                     float* __restrict__ aml,
                                                     int Tk, int Tc, int chunk) {
    __shared__ float sc[8 * ATILE];
    __shared__ __align__(16) float kt[2][KT_F];   // [0]=K, [1]=V
    __shared__ float qs[8 * 68];
    __shared__ float ml[16];

    int h = blockIdx.x, b = blockIdx.y, z = blockIdx.z;
    int k0 = z * chunk;
    int nv = min(Tk, k0 + chunk) - k0;
    if (nv < 0) nv = 0;
    int tid = threadIdx.x, lane = tid & 31, w = tid >> 5;
    uint32_t ktb = smem_to_u32(&kt[0][0]);
    int srow = tid >> 2, sq4 = (tid & 3) * 4;

    stage_rows(ktb, kc, kn, b, h, Tc, k0, nv, srow, sq4);
    CP_COMMIT();
    stage_rows(ktb + (uint32_t)KT_F * 4, vc, vn, b, h, Tc, k0, nv, srow, sq4);
    CP_COMMIT();

    if (tid < 128) {
        int qi = tid >> 4, d4 = (tid & 15) * 4;
        float4 v = *(const float4*)(kq + (size_t)(b * TQ + qi) * DD + h * DH + d4);
        v.x *= 0.125f; v.y *= 0.125f; v.z *= 0.125f; v.w *= 0.125f;
        *(float4*)&qs[qi * 68 + d4] = v;
    }
    __syncthreads();

    uint32_t aA[8], aC[8];
    const uint32_t zr = 0;
    {
        const float* qp = &qs[(lane >> 2) * 68];
#pragma unroll
        for (int s = 0; s < 8; s++) {
            aA[s] = f2tf(qp[s * 8 + (lane & 3)]);
            aC[s] = f2tf(qp[s * 8 + 4 + (lane & 3)]);
        }
    }

    CP_WAIT1();
    __syncthreads();
    {
        float c0[4] = {0.f, 0.f, 0.f, 0.f};
        uint32_t kaddr = ktb + (uint32_t)((w * 8 + (lane & 7)) * 68) * 4 +
                         ((lane >> 3) & 3) * 16;
#pragma unroll
        for (int s = 0; s < 4; s++) {
            uint32_t b0, b1, b2, b3;
            LDMX4(b0, b1, b2, b3, kaddr + s * 64);
            mma_tf32(c0, aA[2 * s], zr, aC[2 * s], zr, b0, b1);
            mma_tf32(c0, aA[2 * s + 1], zr, aC[2 * s + 1], zr, b2, b3);
        }
        int qrow = lane >> 2;
        int key = w * 8 + 2 * (lane & 3);
        if (key < nv) {
            float s0 = c0[0];
            if (mask) s0 += mask[(size_t)qrow * Tk + k0 + key];
            sc[qrow * ATILE + key] = s0;
        }
        if (key + 1 < nv) {
            float s1 = c0[1];
            if (mask) s1 += mask[(size_t)qrow * Tk + k0 + key + 1];
            sc[qrow * ATILE + key + 1] = s1;
        }
    }
    __syncthreads();

    {
        float m = -1e30f;
        for (int k = lane; k < nv; k += 32) m = fmaxf(m, sc[w * ATILE + k]);
        for (int o = 16; o; o >>= 1) m = fmaxf(m, __shfl_xor_sync(~0u, m, o));
        float l = 0.f;
        for (int k = lane; k < nv; k += 32) {
            float e = __expf(sc[w * ATILE + k] - m);
            sc[w * ATILE + k] = e;
            l += e;
        }
        for (int o = 16; o; o >>= 1) l += __shfl_xor_sync(~0u, l, o);
        if (lane == 0) { ml[w * 2] = m; ml[w * 2 + 1] = l; }
    }

    CP_WAIT0();
    __syncthreads();
    float acc[8][2];
#pragma unroll
    for (int qi = 0; qi < 8; qi++) { acc[qi][0] = 0.f; acc[qi][1] = 0.f; }
    {
        const float* vt = &kt[1][0];
        for (int k = w; k < nv; k += 8) {
            float2 v2 = *(const float2*)&vt[k * 68 + 2 * lane];
            const float* sp = &sc[k];
#pragma unroll
            for (int qi = 0; qi < 8; qi++) {
                float p = sp[qi * ATILE];
                acc[qi][0] += p * v2.x;
                acc[qi][1] += p * v2.y;
            }
        }
    }
    __syncthreads();

    float* red = (float*)&kt[0][0];
#pragma unroll
    for (int qi = 0; qi < 8; qi++)
        *(float2*)&red[(w * 8 + qi) * REDS + 2 * lane] = make_float2(acc[qi][0], acc[qi][1]);
    __syncthreads();

    size_t idx = ((size_t)z * BB + b) * HH + h;
    float* ap = apacc + idx * TQ * DH;
    int qi2 = tid >> 5, dp = tid & 31;
    float s0 = 0.f, s1 = 0.f;
#pragma unroll
    for (int ww = 0; ww < 8; ww++) {
        float2 a = *(const float2*)&red[(ww * 8 + qi2) * REDS + 2 * dp];
        s0 += a.x;
        s1 += a.y;
    }
    *(float2*)&ap[qi2 * 64 + 2 * dp] = make_float2(s0, s1);
    if (tid < 16) aml[idx * 16 + tid] = ml[tid];
}

// ---- multi-tile kernel (chunk <= SCP keys per CTA, pipelined tiles) ----
__global__ __launch_bounds__(256) void attn_split_mt(const float* __restrict__ kq,
                                                     const float* __restrict__ kc,
                                                     const float* __restrict__ vc,
                                                     const float* __restrict__ kn,
                                                     const float* __restrict__ vn,
                                                     const float* __restrict__ mask,
                                                     float* __restrict__ apacc,
                                                     float* __restrict__ aml,
                                                     int Tk, int Tc, int chunk) {
    __shared__ float sc[8 * SCP];
    __shared__ __align__(16) float kt[2][KT_F];
    __shared__ float qs[8 * 68];
    __shared__ float ml[16];

    int h = blockIdx.x, b = blockIdx.y, z = blockIdx.z;
    int k0 = z * chunk;
    int nv = min(Tk, k0 + chunk) - k0;
    int tid = threadIdx.x, lane = tid & 31, w = tid >> 5;
    uint32_t ktb = smem_to_u32(&kt[0][0]);

    if (tid < 128) {
        int qi = tid >> 4, d4 = (tid & 15) * 4;
        float4 v = *(const float4*)(kq + (size_t)(b * TQ + qi) * DD + h * DH + d4);
        v.x *= 0.125f; v.y *= 0.125f; v.z *= 0.125f; v.w *= 0.125f;
        *(float4*)&qs[qi * 68 + d4] = v;
    }
    __syncthreads();

    uint32_t aA[8], aC[8];
    const uint32_t zr = 0;
    {
        const float* qp = &qs[(lane >> 2) * 68];
#pragma unroll
        for (int s = 0; s < 8; s++) {
            aA[s] = f2tf(qp[s * 8 + (lane & 3)]);
            aC[s] = f2tf(qp[s * 8 + 4 + (lane & 3)]);
        }
    }

    int srow = tid >> 2, sq4 = (tid & 3) * 4;
    int nt = (nv + ATILE - 1) / ATILE;
    uint32_t kfrag_off = (uint32_t)((w * 8 + (lane & 7)) * 68) * 4 + ((lane >> 3) & 3) * 16;

    // ==== pass 1: scores via mma ====
    stage_rows(ktb, kc, kn, b, h, Tc, k0, min(ATILE, nv), srow, sq4);
    CP_COMMIT();
    for (int t = 0; t < nt; t++) {
        int kb = t * ATILE;
        int nk = min(ATILE, nv - kb);
        if (t + 1 < nt) {
            stage_rows(ktb + (uint32_t)(((t + 1) & 1) * KT_F) * 4, kc, kn, b, h, Tc,
                       k0 + kb + ATILE, min(ATILE, nv - kb - ATILE), srow, sq4);
            CP_COMMIT();
            CP_WAIT1();
        } else {
            CP_WAIT0();
        }
        __syncthreads();
        float c0[4] = {0.f, 0.f, 0.f, 0.f};
        uint32_t kaddr = ktb + (uint32_t)((t & 1) * KT_F) * 4 + kfrag_off;
#pragma unroll
        for (int s = 0; s < 4; s++) {
            uint32_t b0, b1, b2, b3;
            LDMX4(b0, b1, b2, b3, kaddr + s * 64);
            mma_tf32(c0, aA[2 * s], zr, aC[2 * s], zr, b0, b1);
            mma_tf32(c0, aA[2 * s + 1], zr, aC[2 * s + 1], zr, b2, b3);
        }
        int qrow = lane >> 2;
        int key = w * 8 + 2 * (lane & 3);
        if (key < nk) {
            float s0 = c0[0];
            if (mask) s0 += mask[(size_t)qrow * Tk + k0 + kb + key];
            sc[qrow * SCP + kb + key] = s0;
        }
        if (key + 1 < nk) {
            float s1 = c0[1];
            if (mask) s1 += mask[(size_t)qrow * Tk + k0 + kb + key + 1];
            sc[qrow * SCP + kb + key + 1] = s1;
        }
        __syncthreads();
    }

    // V tile 0 prefetch under softmax
    stage_rows(ktb + (uint32_t)((nt & 1) * KT_F) * 4, vc, vn, b, h, Tc,
               k0, min(ATILE, nv), srow, sq4);
    CP_COMMIT();

    {
        float m = -1e30f;
        for (int k = lane; k < nv; k += 32) m = fmaxf(m, sc[w * SCP + k]);
        for (int o = 16; o; o >>= 1) m = fmaxf(m, __shfl_xor_sync(~0u, m, o));
        float l = 0.f;
        for (int k = lane; k < nv; k += 32) {
            float e = __expf(sc[w * SCP + k] - m);
            sc[w * SCP + k] = e;
            l += e;
        }
        for (int o = 16; o; o >>= 1) l += __shfl_xor_sync(~0u, l, o);
        if (lane == 0) { ml[w * 2] = m; ml[w * 2 + 1] = l; }
    }
    __syncthreads();

    // ==== pass 2: AV, warp-striped keys ====
    float acc[8][2];
#pragma unroll
    for (int qi = 0; qi < 8; qi++) { acc[qi][0] = 0.f; acc[qi][1] = 0.f; }

    for (int t = 0; t < nt; t++) {
        int kb = t * ATILE;
        int nk = min(ATILE, nv - kb);
        int cbuf = (t + nt) & 1;
        if (t + 1 < nt) {
            stage_rows(ktb + (uint32_t)(((t + 1 + nt) & 1) * KT_F) * 4, vc, vn, b, h, Tc,
                       k0 + kb + ATILE, min(ATILE, nv - kb - ATILE), srow, sq4);
            CP_COMMIT();
            CP_WAIT1();
        } else {
            CP_WAIT0();
        }
        __syncthreads();
        const float* vt = &kt[cbuf][0];
        for (int k = w; k < nk; k += 8) {
            float2 v2 = *(const float2*)&vt[k * 68 + 2 * lane];
            const float* sp = &sc[kb + k];
#pragma unroll
            for (int qi = 0; qi < 8; qi++) {
                float p = sp[qi * SCP];
                acc[qi][0] += p * v2.x;
                acc[qi][1] += p * v2.y;
            }
        }
        __syncthreads();
    }

    float* red = (float*)&kt[0][0];
#pragma unroll
    for (int qi = 0; qi < 8; qi++)
        *(float2*)&red[(w * 8 + qi) * REDS + 2 * lane] = make_float2(acc[qi][0], acc[qi][1]);
    __syncthreads();

    size_t idx = ((size_t)z * BB + b) * HH + h;
    float* ap = apacc + idx * TQ * DH;
    int qi2 = tid >> 5, dp = tid & 31;
    float s0 = 0.f, s1 = 0.f;
#pragma unroll
    for (int ww = 0; ww < 8; ww++) {
        float2 a = *(const float2*)&red[(ww * 8 + qi2) * REDS + 2 * dp];
        s0 += a.x;
        s1 += a.y;
    }
    *(float2*)&ap[qi2 * 64 + 2 * dp] = make_float2(s0, s1);
    if (tid < 16) aml[idx * 16 + tid] = ml[tid];
}

// ---------------- attention combine ----------------
__global__ __launch_bounds__(256) void attn_combine(const float* __restrict__ apacc,
                                                    const float* __restrict__ aml,
                                                    float* __restrict__ out, int S) {
    int h = blockIdx.x, b = blockIdx.y;
    int tid = threadIdx.x;
    int qi = tid >> 5, dp = tid & 31;
    float mstar = -1e30f;
    for (int z = 0; z < S; z++) {
        size_t idx = ((size_t)z * BB + b) * HH + h;
        mstar = fmaxf(mstar, aml[idx * 16 + qi * 2]);
    }
    float den = 0.f, n0 = 0.f, n1 = 0.f;
    for (int z = 0; z < S; z++) {
        size_t idx = ((size_t)z * BB + b) * HH + h;
        float mz = aml[idx * 16 + qi * 2];
        float lz = aml[idx * 16 + qi * 2 + 1];
        float s = __expf(mz - mstar);
        den += lz * s;
        float2 a = *(const float2*)&apacc[idx * TQ * DH + qi * 64 + dp * 2];
        n0 += a.x * s;
        n1 += a.y * s;
    }
    float inv = 1.f / den;
    float* o = out + (size_t)(b * TQ + qi) * DD + h * DH + dp * 2;
    o[0] = n0 * inv;
    o[1] = n1 * inv;
}

// ---------------- host orchestration ----------------
extern "C" void kernel_launch(void* const* d_in, const int* in_sizes, int n_in,
                              void* d_out, int out_size) {
    const float* x            = (const float*)d_in[0];
    const float* self_k_cache = (const float*)d_in[1];
    const float* self_v_cache = (const float*)d_in[2];
    const float* cross_k      = (const float*)d_in[3];
    const float* cross_v      = (const float*)d_in[4];
    const float* mask         = (const float*)d_in[5];
    const float* attn_wq = (const float*)d_in[6];
    const float* attn_bq = (const float*)d_in[7];
    const float* attn_wk = (const float*)d_in[8];
    const float* attn_wv = (const float*)d_in[9];
    const float* attn_bv = (const float*)d_in[10];
    const float* attn_wo = (const float*)d_in[11];
    const float* attn_bo = (const float*)d_in[12];
    const float* cross_wq = (const float*)d_in[13];
    const float* cross_bq = (const float*)d_in[14];
    const float* cross_wo = (const float*)d_in[15];
    const float* cross_bo = (const float*)d_in[16];
    const float* attn_ln_w = (const float*)d_in[17];
    const float* attn_ln_b = (const float*)d_in[18];
    const float* cross_ln_w = (const float*)d_in[19];
    const float* cross_ln_b = (const float*)d_in[20];
    const float* mlp_ln_w = (const float*)d_in[21];
    const float* mlp_ln_b = (const float*)d_in[22];
    const float* mlp_w1 = (const float*)d_in[23];
    const float* mlp_b1 = (const float*)d_in[24];
    const float* mlp_w2 = (const float*)d_in[25];
    const float* mlp_b2 = (const float*)d_in[26];

    float* out_x  = (float*)d_out;
    float* out_k1 = out_x + MM * DD;
    float* out_v1 = out_k1 + MM * DD;

    float *g_xl, *g_q, *g_attn, *g_x1, *g_h, *g_part, *g_apacc, *g_aml;
    cudaGetSymbolAddress((void**)&g_xl, g_xl_);
    cudaGetSymbolAddress((void**)&g_q, g_q_);
    cudaGetSymbolAddress((void**)&g_attn, g_attn_);
    cudaGetSymbolAddress((void**)&g_x1, g_x1_);
    cudaGetSymbolAddress((void**)&g_h, g_h_);
    cudaGetSymbolAddress((void**)&g_part, g_part_);
    cudaGetSymbolAddress((void**)&g_apacc, g_apacc_);
    cudaGetSymbolAddress((void**)&g_aml, g_aml_);

    const int MN_D = MM * DD;        // 81920
    const int MN_F = MM * DFF;       // 327680
    dim3 blk(256);

    dim3 gQKV(DD / 64, 3, 10);   // fused QKV: kc=128 (4 stages), 600 CTAs
    dim3 gD(DD / 64, 1, 20);     // D GEMM: kc=64 (2 stages), 400 CTAs
    dim3 gF1(DFF / 64, 1, 8);    // MLP1: kc=160 (5 stages), 640 CTAs
    dim3 gF2(DD / 64, 1, 20);    // MLP2: kc=256 (8 stages), 400 CTAs
    int redD = (MN_D + 255) / 256;
    int redF = (MN_F + 255) / 256;

    int S_SELF = 8, CH_SELF = (TK_SELF + S_SELF - 1) / S_SELF;   // 57 (<=64, 1-tile)
    int S_CROSS = 12, CH_CROSS = (TC + S_CROSS - 1) / S_CROSS;   // 125 (2 tiles)

    // --- self-attention block ---
    ln_kernel<<<MM, blk>>>(x, attn_ln_w, attn_ln_b, g_xl);

    gemm_mma<<<gQKV, blk>>>(g_xl, attn_wq, attn_wk, attn_wv, g_part, DD, DD, 128);
    reduce_epi<<<dim3(redD, 3), blk>>>(g_part, 10, MN_D, DD,
                                       attn_bq, nullptr, attn_bv, nullptr,
                                       g_q, out_k1, out_v1, 0);

    attn_split_1t<<<dim3(HH, BB, S_SELF), blk>>>(g_q, self_k_cache, self_v_cache,
                                                 out_k1, out_v1, mask,
                                                 g_apacc, g_aml, TK_SELF, TP, CH_SELF);
    attn_combine<<<dim3(HH, BB), blk>>>(g_apacc, g_aml, g_attn, S_SELF);

    gemm_mma<<<gD, blk>>>(g_attn, attn_wo, attn_wo, attn_wo, g_part, DD, DD, 64);
    reduce_epi<<<dim3(redD, 1), blk>>>(g_part, 20, MN_D, DD,
                                       attn_bo, nullptr, nullptr, x,
                                       g_x1, nullptr, nullptr, 0);

    // --- cross-attention block ---
    ln_kernel<<<MM, blk>>>(g_x1, cross_ln_w, cross_ln_b, g_xl);

    gemm_mma<<<gD, blk>>>(g_xl, cross_wq, cross_wq, cross_wq, g_part, DD, DD, 64);
    reduce_epi<<<dim3(redD, 1), blk>>>(g_part, 20, MN_D, DD,
                                       cross_bq, nullptr, nullptr, nullptr,
                                       g_q, nullptr, nullptr, 0);

    attn_split_mt<<<dim3(HH, BB, S_CROSS), blk>>>(g_q, cross_k, cross_v,
                                                  nullptr, nullptr, nullptr,
                                                  g_apacc, g_aml, TC, TC, CH_CROSS);
    attn_combine<<<dim3(HH, BB), blk>>>(g_apacc, g_aml, g_attn, S_CROSS);

    gemm_mma<<<gD, blk>>>(g_attn, cross_wo, cross_wo, cross_wo, g_part, DD, DD, 64);
    reduce_epi<<<dim3(redD, 1), blk>>>(g_part, 20, MN_D, DD,
                                       cross_bo, nullptr, nullptr, g_x1,
                                       out_x, nullptr, nullptr, 0);

    // --- MLP block ---
    ln_kernel<<<MM, blk>>>(out_x, mlp_ln_w, mlp_ln_b, g_xl);

    gemm_mma<<<gF1, blk>>>(g_xl, mlp_w1, mlp_w1, mlp_w1, g_part, DD, DFF, 160);
    reduce_epi<<<dim3(redF, 1), blk>>>(g_part, 8, MN_F, DFF,
                                       mlp_b1, nullptr, nullptr, nullptr,
                                       g_h, nullptr, nullptr, 1);

    gemm_mma<<<gF2, blk>>>(g_h, mlp_w2, mlp_w2, mlp_w2, g_part, DFF, DD, 256);
    reduce_epi<<<dim3(redD, 1), blk>>>(g_part, 20, MN_D, DD,
                                       mlp_b2, nullptr, nullptr, out_x,
                                       out_x, nullptr, nullptr, 0);
}